// round 1
// baseline (speedup 1.0000x reference)
#include <cuda_runtime.h>
#include <math.h>

#define NB 256
#define NT 1024
#define ND0 32
#define NH 64
#define NG 256

// Scratch for layer-0 hidden sequence (allowed: __device__ global, no cudaMalloc)
__device__ float g_h1[(size_t)NB * NT * NH];

__device__ __forceinline__ float sigf(float x) { return 1.0f / (1.0f + __expf(-x)); }

// One CTA = 2 samples, 256 threads, each thread owns gates (lane, lane+128) of its sample.
// U = DIN + NH combined input vector [x_t ; h_{t-1}]; W = [w_ih | w_hh] packed in smem as
// float4 tiles Wp[k4][gate] so each thread does conflict-free LDS.128.
template <int DIN, int LAYER>
__global__ __launch_bounds__(256) void lstm_layer(
    const float* __restrict__ xin,    // LAYER==0: x [B][T][DIN]; LAYER==1: unused
    const float* __restrict__ w_ih,   // [G][DIN]
    const float* __restrict__ w_hh,   // [G][NH]
    const float* __restrict__ b_ih,   // [G]
    const float* __restrict__ b_hh,   // [G]
    const float* __restrict__ w_fc,   // [1][NH]   (LAYER==1 only)
    const float* __restrict__ b_fc,   // [1]       (LAYER==1 only)
    float* __restrict__ out)          // [B]       (LAYER==1 only)
{
    constexpr int U  = DIN + NH;   // 96 (L0) or 128 (L1)
    constexpr int K4 = U / 4;      // 24 or 32

    extern __shared__ float smem[];
    float4* Wp   = reinterpret_cast<float4*>(smem);        // K4*NG float4
    float*  ubuf = smem + (size_t)K4 * NG * 4;             // 2 * U
    float*  gbuf = ubuf + 2 * U;                           // 2 * NG
    float*  rbuf = gbuf + 2 * NG;                          // 4 (fc reduce)

    const int tid  = threadIdx.x;
    const int s    = tid >> 7;        // sample slot within CTA (0/1)
    const int lane = tid & 127;       // 0..127 within sample
    const int j0   = lane;            // gate 0
    const int j1   = lane + 128;      // gate 1
    const int b    = (blockIdx.x << 1) + s;

    // ---- load packed weights into smem: Wp[k4*NG + j] = {W[j][4k4..4k4+3]} ----
    for (int idx = tid; idx < K4 * NG; idx += 256) {
        const int k4 = idx / NG;
        const int j  = idx - k4 * NG;
        float4 v;
#pragma unroll
        for (int c = 0; c < 4; c++) {
            const int k = k4 * 4 + c;
            reinterpret_cast<float*>(&v)[c] =
                (k < DIN) ? w_ih[j * DIN + k] : w_hh[j * NH + (k - DIN)];
        }
        Wp[idx] = v;
    }

    const float bias0 = b_ih[j0] + b_hh[j0];
    const float bias1 = b_ih[j1] + b_hh[j1];

    if (lane < NH) ubuf[s * U + DIN + lane] = 0.0f;   // h0 = 0

    const float* src = (LAYER == 0) ? (xin + (size_t)b * NT * DIN)
                                    : (g_h1 + (size_t)b * NT * NH);
    float* hdst = (LAYER == 0) ? (g_h1 + (size_t)b * NT * NH) : nullptr;

    float c_state = 0.0f;   // valid for lane < NH
    float h_last  = 0.0f;

    __syncthreads();

    for (int t = 0; t < NT; t++) {
        // stage x_t (or h1_t) into u[0..DIN)
        if (lane < DIN / 4) {
            reinterpret_cast<float4*>(ubuf + s * U)[lane] =
                reinterpret_cast<const float4*>(src + t * DIN)[lane];
        }
        __syncthreads();

        // gate dot products: g_j = bias_j + sum_k u[k] * W[j][k]
        float a0 = bias0, a1 = bias1, a2 = 0.0f, a3 = 0.0f;
        const float4* us = reinterpret_cast<const float4*>(ubuf + s * U);
#pragma unroll
        for (int k4 = 0; k4 < K4; k4 += 2) {
            const float4 u0 = us[k4];
            const float4 u1 = us[k4 + 1];
            const float4 wa = Wp[k4 * NG + j0];
            const float4 wb = Wp[k4 * NG + j1];
            const float4 wc = Wp[(k4 + 1) * NG + j0];
            const float4 wd = Wp[(k4 + 1) * NG + j1];
            a0 = fmaf(u0.x, wa.x, a0); a0 = fmaf(u0.y, wa.y, a0);
            a0 = fmaf(u0.z, wa.z, a0); a0 = fmaf(u0.w, wa.w, a0);
            a1 = fmaf(u0.x, wb.x, a1); a1 = fmaf(u0.y, wb.y, a1);
            a1 = fmaf(u0.z, wb.z, a1); a1 = fmaf(u0.w, wb.w, a1);
            a2 = fmaf(u1.x, wc.x, a2); a2 = fmaf(u1.y, wc.y, a2);
            a2 = fmaf(u1.z, wc.z, a2); a2 = fmaf(u1.w, wc.w, a2);
            a3 = fmaf(u1.x, wd.x, a3); a3 = fmaf(u1.y, wd.y, a3);
            a3 = fmaf(u1.z, wd.z, a3); a3 = fmaf(u1.w, wd.w, a3);
        }
        gbuf[s * NG + j0] = a0 + a2;
        gbuf[s * NG + j1] = a1 + a3;
        __syncthreads();

        // pointwise LSTM cell (PyTorch gate order i, f, g, o)
        if (lane < NH) {
            const float gi = gbuf[s * NG + lane];
            const float gf = gbuf[s * NG + NH + lane];
            const float gg = gbuf[s * NG + 2 * NH + lane];
            const float go = gbuf[s * NG + 3 * NH + lane];
            c_state = sigf(gf) * c_state + sigf(gi) * tanhf(gg);
            const float h = sigf(go) * tanhf(c_state);
            h_last = h;
            ubuf[s * U + DIN + lane] = h;      // next step's h (read after next barrier)
            if (LAYER == 0) hdst[t * NH + lane] = h;
        }
    }

    if (LAYER == 1) {
        // out[b] = sigmoid( h_last . w_fc + b_fc ), reduce over the sample's 64 lanes
        float p = (lane < NH) ? h_last * w_fc[lane] : 0.0f;
#pragma unroll
        for (int off = 16; off > 0; off >>= 1)
            p += __shfl_down_sync(0xffffffffu, p, off);
        __syncthreads();
        if ((tid & 31) == 0 && lane < NH)
            rbuf[s * 2 + ((lane >> 5) & 1)] = p;   // two warps per sample contribute
        __syncthreads();
        if (lane == 0)
            out[b] = sigf(rbuf[s * 2] + rbuf[s * 2 + 1] + b_fc[0]);
    }
}

extern "C" void kernel_launch(void* const* d_in, const int* in_sizes, int n_in,
                              void* d_out, int out_size) {
    const float* x       = (const float*)d_in[0];
    const float* w_ih_l0 = (const float*)d_in[1];
    const float* w_hh_l0 = (const float*)d_in[2];
    const float* b_ih_l0 = (const float*)d_in[3];
    const float* b_hh_l0 = (const float*)d_in[4];
    const float* w_ih_l1 = (const float*)d_in[5];
    const float* w_hh_l1 = (const float*)d_in[6];
    const float* b_ih_l1 = (const float*)d_in[7];
    const float* b_hh_l1 = (const float*)d_in[8];
    const float* w_fc    = (const float*)d_in[9];
    const float* b_fc    = (const float*)d_in[10];
    float* out = (float*)d_out;

    constexpr size_t smem0 = (size_t)(96 / 4) * NG * 16 + (2 * 96 + 2 * NG + 16) * 4;
    constexpr size_t smem1 = (size_t)(128 / 4) * NG * 16 + (2 * 128 + 2 * NG + 16) * 4;

    cudaFuncSetAttribute(lstm_layer<ND0, 0>,
                         cudaFuncAttributeMaxDynamicSharedMemorySize, (int)smem0);
    cudaFuncSetAttribute(lstm_layer<NH, 1>,
                         cudaFuncAttributeMaxDynamicSharedMemorySize, (int)smem1);

    lstm_layer<ND0, 0><<<NB / 2, 256, smem0>>>(
        x, w_ih_l0, w_hh_l0, b_ih_l0, b_hh_l0, nullptr, nullptr, nullptr);

    lstm_layer<NH, 1><<<NB / 2, 256, smem1>>>(
        nullptr, w_ih_l1, w_hh_l1, b_ih_l1, b_hh_l1, w_fc, b_fc, out);
}

// round 2
// speedup vs baseline: 1.7005x; 1.7005x over previous
#include <cuda_runtime.h>
#include <math.h>

#define NB 256
#define NT 1024
#define ND0 32
#define NH 64
#define NG 256

// Scratch for layer-0 hidden sequence (device global — no allocation)
__device__ float g_h1[(size_t)NB * NT * NH];

__device__ __forceinline__ float sigf(float x)   { return 1.0f / (1.0f + __expf(-x)); }
__device__ __forceinline__ float tanhf_(float x) { return 2.0f * sigf(2.0f * x) - 1.0f; }

// One CTA = 2 samples, 256 threads. Thread j owns gate j; its weight row
// W[j][0..U) = [w_ih[j] | w_hh[j]] lives entirely in REGISTERS (no smem weight
// traffic). Each thread computes gate j for both samples per step. The only
// hot-loop smem reads are broadcast LDS.128 of the u-vector [x_t ; h_{t-1}].
template <int DIN, int LAYER>
__global__ __launch_bounds__(256) void lstm_layer(
    const float* __restrict__ xin,    // LAYER==0: x [B][T][DIN]
    const float* __restrict__ w_ih,   // [G][DIN]
    const float* __restrict__ w_hh,   // [G][NH]
    const float* __restrict__ b_ih,   // [G]
    const float* __restrict__ b_hh,   // [G]
    const float* __restrict__ w_fc,   // [1][NH]  (LAYER==1)
    const float* __restrict__ b_fc,   // [1]      (LAYER==1)
    float* __restrict__ out)          // [B]      (LAYER==1)
{
    constexpr int U   = DIN + NH;     // 96 (L0) / 128 (L1)
    constexpr int K4  = U / 4;        // 24 / 32
    constexpr int NX4 = DIN / 4;      // x-part float4 count per sample

    __shared__ float ubuf[2 * U];     // per-sample [x_t ; h]
    __shared__ float gbuf[2 * NG];    // per-sample gate pre-activations
    __shared__ float rbuf[4];         // fc partial sums

    const int tid = threadIdx.x;
    const int j   = tid;              // gate index
    const int b0  = blockIdx.x * 2;

    // ---- weight row for gate j -> registers (fully unrolled, static idx) ----
    float4 wreg[K4];
#pragma unroll
    for (int k4 = 0; k4 < K4; k4++) {
        float4 v;
#pragma unroll
        for (int c = 0; c < 4; c++) {
            const int k = k4 * 4 + c;
            reinterpret_cast<float*>(&v)[c] =
                (k < DIN) ? w_ih[j * DIN + k] : w_hh[j * NH + (k - DIN)];
        }
        wreg[k4] = v;
    }
    const float bias = b_ih[j] + b_hh[j];

    // roles
    const int  ls = tid >> 7;         // loader's sample (0/1)
    const int  li = tid & 127;
    const bool isload = (li < NX4);   // stages x_t for its sample
    const bool iscell = (tid < 128);  // pointwise cell lanes
    const int  cs = tid >> 6;         // cell's sample (valid when iscell)
    const int  cl = tid & 63;         // cell's h-lane
    float* hdst = g_h1 + (size_t)(b0 + cs) * NT * NH;

    const float* src = (LAYER == 0) ? xin + (size_t)(b0 + ls) * NT * DIN
                                    : g_h1 + (size_t)(b0 + ls) * NT * NH;

    if (li < NH) ubuf[ls * U + DIN + li] = 0.0f;     // h0 = 0

    float4 xr;                                        // prefetched x_t
    if (isload) xr = reinterpret_cast<const float4*>(src)[li];

    float c_state = 0.0f, h_last = 0.0f;

    for (int t = 0; t < NT; t++) {
        // stage prefetched x_t (h_{t-1} was written at end of prev iter)
        if (isload) reinterpret_cast<float4*>(ubuf + ls * U)[li] = xr;
        __syncthreads();
        // prefetch next timestep's input (latency hidden under the dots)
        if (isload && t + 1 < NT)
            xr = reinterpret_cast<const float4*>(src + (t + 1) * DIN)[li];

        // gate j dot products for both samples, weights in registers
        float a00 = bias, a01 = 0.0f, a10 = bias, a11 = 0.0f;
        const float4* u0 = reinterpret_cast<const float4*>(ubuf);
        const float4* u1 = reinterpret_cast<const float4*>(ubuf + U);
#pragma unroll
        for (int k4 = 0; k4 < K4; k4 += 2) {
            const float4 p0 = u0[k4], q0 = u0[k4 + 1];
            const float4 p1 = u1[k4], q1 = u1[k4 + 1];
            const float4 w0 = wreg[k4], w1 = wreg[k4 + 1];
            a00 = fmaf(p0.x, w0.x, a00); a00 = fmaf(p0.y, w0.y, a00);
            a00 = fmaf(p0.z, w0.z, a00); a00 = fmaf(p0.w, w0.w, a00);
            a01 = fmaf(q0.x, w1.x, a01); a01 = fmaf(q0.y, w1.y, a01);
            a01 = fmaf(q0.z, w1.z, a01); a01 = fmaf(q0.w, w1.w, a01);
            a10 = fmaf(p1.x, w0.x, a10); a10 = fmaf(p1.y, w0.y, a10);
            a10 = fmaf(p1.z, w0.z, a10); a10 = fmaf(p1.w, w0.w, a10);
            a11 = fmaf(q1.x, w1.x, a11); a11 = fmaf(q1.y, w1.y, a11);
            a11 = fmaf(q1.z, w1.z, a11); a11 = fmaf(q1.w, w1.w, a11);
        }
        gbuf[j]      = a00 + a01;     // sample 0
        gbuf[NG + j] = a10 + a11;     // sample 1
        __syncthreads();

        // pointwise LSTM cell (gate order i, f, g, o)
        if (iscell) {
            const float* gb = gbuf + cs * NG;
            const float gi = gb[cl];
            const float gf = gb[NH + cl];
            const float gg = gb[2 * NH + cl];
            const float go = gb[3 * NH + cl];
            c_state = sigf(gf) * c_state + sigf(gi) * tanhf_(gg);
            const float h = sigf(go) * tanhf_(c_state);
            h_last = h;
            ubuf[cs * U + DIN + cl] = h;             // next step's h
            if (LAYER == 0) hdst[t * NH + cl] = h;
        }
    }

    if (LAYER == 1) {
        // out[b] = sigmoid(h_last . w_fc + b_fc); 64 lanes/sample = 2 warps
        if (iscell) {
            float p = h_last * w_fc[cl];
#pragma unroll
            for (int o = 16; o > 0; o >>= 1)
                p += __shfl_down_sync(0xffffffffu, p, o);
            if ((tid & 31) == 0) rbuf[tid >> 5] = p;
        }
        __syncthreads();
        if (tid < 2)
            out[b0 + tid] = sigf(rbuf[tid * 2] + rbuf[tid * 2 + 1] + b_fc[0]);
    }
}

extern "C" void kernel_launch(void* const* d_in, const int* in_sizes, int n_in,
                              void* d_out, int out_size) {
    const float* x       = (const float*)d_in[0];
    const float* w_ih_l0 = (const float*)d_in[1];
    const float* w_hh_l0 = (const float*)d_in[2];
    const float* b_ih_l0 = (const float*)d_in[3];
    const float* b_hh_l0 = (const float*)d_in[4];
    const float* w_ih_l1 = (const float*)d_in[5];
    const float* w_hh_l1 = (const float*)d_in[6];
    const float* b_ih_l1 = (const float*)d_in[7];
    const float* b_hh_l1 = (const float*)d_in[8];
    const float* w_fc    = (const float*)d_in[9];
    const float* b_fc    = (const float*)d_in[10];
    float* out = (float*)d_out;

    lstm_layer<ND0, 0><<<NB / 2, 256>>>(
        x, w_ih_l0, w_hh_l0, b_ih_l0, b_hh_l0, nullptr, nullptr, nullptr);

    lstm_layer<NH, 1><<<NB / 2, 256>>>(
        nullptr, w_ih_l1, w_hh_l1, b_ih_l1, b_hh_l1, w_fc, b_fc, out);
}

// round 3
// speedup vs baseline: 1.8460x; 1.0856x over previous
#include <cuda_runtime.h>
#include <math.h>

#define NB 256
#define NT 1024
#define ND0 32
#define NH 64
#define NG 256

__device__ float g_h1[(size_t)NB * NT * NH];

__device__ __forceinline__ float sigf(float x)   { return 1.0f / (1.0f + __expf(-x)); }
__device__ __forceinline__ float tanhf_(float x) { return 2.0f * sigf(2.0f * x) - 1.0f; }

__device__ __forceinline__ void ffma2(unsigned long long& d,
                                      unsigned long long a,
                                      unsigned long long b) {
    asm("fma.rn.f32x2 %0, %1, %2, %0;" : "+l"(d) : "l"(a), "l"(b));
}
__device__ __forceinline__ unsigned long long packf2(float x, float y) {
    unsigned long long r;
    asm("mov.b64 %0, {%1, %2};" : "=l"(r) : "f"(x), "f"(y));
    return r;
}
__device__ __forceinline__ float2 unpackf2(unsigned long long v) {
    float2 f;
    asm("mov.b64 {%0, %1}, %2;" : "=f"(f.x), "=f"(f.y) : "l"(v));
    return f;
}

// One CTA = 2 samples, 512 threads. Thread (j = tid>>1, half = tid&1) owns one
// k-half of gate j's weight row in REGISTERS and computes partial gate dots for
// both samples using packed f32x2 FMAs. Halves combine via shfl_xor(1).
// u = [x_t ; h_{t-1}] per sample in smem; hi half padded +4 floats (bank shift
// + 16B alignment). Only broadcast LDS.128 in the hot loop.
template <int DIN, int LAYER>
__global__ __launch_bounds__(512) void lstm_layer(
    const float* __restrict__ xin,
    const float* __restrict__ w_ih,   // [G][DIN]
    const float* __restrict__ w_hh,   // [G][NH]
    const float* __restrict__ b_ih,
    const float* __restrict__ b_hh,
    const float* __restrict__ w_fc,   // [1][NH]  (LAYER==1)
    const float* __restrict__ b_fc,   // [1]      (LAYER==1)
    float* __restrict__ out)          // [B]      (LAYER==1)
{
    constexpr int U    = DIN + NH;      // 96 / 128
    constexpr int HALF = U / 2;         // 48 / 64
    constexpr int H2   = HALF / 2;      // f32x2 weight pairs per thread
    constexpr int H4   = HALF / 4;      // ulonglong2 loads per sample
    constexpr int HIB  = HALF + 4;      // hi-half base (floats), 16B aligned
    constexpr int US   = U + 8;         // per-sample stride (floats)
    constexpr int NX4  = DIN / 4;

    __shared__ float ubuf[2 * US];
    __shared__ float gbuf[2 * NG];
    __shared__ float rbuf[4];

    const int tid  = threadIdx.x;
    const int j    = tid >> 1;          // gate index
    const int half = tid & 1;           // k-half
    const int b0   = blockIdx.x * 2;

    // ---- my half of gate j's weight row -> packed f32x2 registers ----
    unsigned long long wreg[H2];
#pragma unroll
    for (int i = 0; i < H2; i++) {
        const int k = half * HALF + 2 * i;
        const float w0 = (k     < DIN) ? w_ih[j * DIN + k]     : w_hh[j * NH + (k     - DIN)];
        const float w1 = (k + 1 < DIN) ? w_ih[j * DIN + k + 1] : w_hh[j * NH + (k + 1 - DIN)];
        wreg[i] = packf2(w0, w1);
    }
    const float bias = b_ih[j] + b_hh[j];

    // roles
    const bool iscell = (tid < 128);
    const int  cs = tid >> 6;           // cell sample
    const int  cl = tid & 63;           // cell h-lane
    bool isload = false; int ls = 0, li = 0;
    if (tid >= 128 && tid < 128 + NX4)      { isload = true; ls = 0; li = tid - 128; }
    else if (tid >= 160 && tid < 160 + NX4) { isload = true; ls = 1; li = tid - 160; }

    float* hdst = g_h1 + (size_t)(b0 + cs) * NT * NH;
    const float* src = (LAYER == 0) ? xin + (size_t)(b0 + ls) * NT * DIN
                                    : g_h1 + (size_t)(b0 + ls) * NT * NH;

    // zero u (covers h0 = 0 and padding)
    for (int i = tid; i < 2 * US; i += 512) ubuf[i] = 0.0f;

    float4 xr;
    if (isload) xr = reinterpret_cast<const float4*>(src)[li];

    float c_state = 0.0f, h_last = 0.0f;

    const ulonglong2* uA = reinterpret_cast<const ulonglong2*>(ubuf + (half ? HIB : 0));
    const ulonglong2* uB = reinterpret_cast<const ulonglong2*>(ubuf + US + (half ? HIB : 0));

    for (int t = 0; t < NT; t++) {
        if (isload) reinterpret_cast<float4*>(ubuf + ls * US)[li] = xr;
        __syncthreads();
        if (isload && t + 1 < NT)
            xr = reinterpret_cast<const float4*>(src + (t + 1) * DIN)[li];

        // partial gate dots, packed dual-fp32 FMA
        unsigned long long p00 = 0, p01 = 0, p10 = 0, p11 = 0;
#pragma unroll
        for (int i = 0; i < H4; i++) {
            const ulonglong2 va = uA[i];
            const ulonglong2 vb = uB[i];
            ffma2(p00, va.x, wreg[2 * i]);
            ffma2(p01, va.y, wreg[2 * i + 1]);
            ffma2(p10, vb.x, wreg[2 * i]);
            ffma2(p11, vb.y, wreg[2 * i + 1]);
        }
        float2 f;
        f = unpackf2(p00); float v0 = f.x + f.y;
        f = unpackf2(p01); v0 += f.x + f.y;
        f = unpackf2(p10); float v1 = f.x + f.y;
        f = unpackf2(p11); v1 += f.x + f.y;
        v0 += __shfl_xor_sync(0xffffffffu, v0, 1);   // combine k-halves
        v1 += __shfl_xor_sync(0xffffffffu, v1, 1);
        if (!half) {
            gbuf[j]      = v0 + bias;
            gbuf[NG + j] = v1 + bias;
        }
        __syncthreads();

        // pointwise LSTM cell (gate order i, f, g, o)
        if (iscell) {
            const float* gb = gbuf + cs * NG;
            const float gi = gb[cl];
            const float gf = gb[NH + cl];
            const float gg = gb[2 * NH + cl];
            const float go = gb[3 * NH + cl];
            c_state = sigf(gf) * c_state + sigf(gi) * tanhf_(gg);
            const float h = sigf(go) * tanhf_(c_state);
            h_last = h;
            const int k = DIN + cl;
            ubuf[cs * US + k + ((k >= HALF) ? 4 : 0)] = h;   // next step's h
            if (LAYER == 0) hdst[t * NH + cl] = h;
        }
    }

    if (LAYER == 1) {
        if (iscell) {
            float p = h_last * w_fc[cl];
#pragma unroll
            for (int o = 16; o > 0; o >>= 1)
                p += __shfl_down_sync(0xffffffffu, p, o);
            if ((tid & 31) == 0) rbuf[tid >> 5] = p;
        }
        __syncthreads();
        if (tid < 2)
            out[b0 + tid] = sigf(rbuf[tid * 2] + rbuf[tid * 2 + 1] + b_fc[0]);
    }
}

extern "C" void kernel_launch(void* const* d_in, const int* in_sizes, int n_in,
                              void* d_out, int out_size) {
    const float* x       = (const float*)d_in[0];
    const float* w_ih_l0 = (const float*)d_in[1];
    const float* w_hh_l0 = (const float*)d_in[2];
    const float* b_ih_l0 = (const float*)d_in[3];
    const float* b_hh_l0 = (const float*)d_in[4];
    const float* w_ih_l1 = (const float*)d_in[5];
    const float* w_hh_l1 = (const float*)d_in[6];
    const float* b_ih_l1 = (const float*)d_in[7];
    const float* b_hh_l1 = (const float*)d_in[8];
    const float* w_fc    = (const float*)d_in[9];
    const float* b_fc    = (const float*)d_in[10];
    float* out = (float*)d_out;

    lstm_layer<ND0, 0><<<NB / 2, 512>>>(
        x, w_ih_l0, w_hh_l0, b_ih_l0, b_hh_l0, nullptr, nullptr, nullptr);

    lstm_layer<NH, 1><<<NB / 2, 512>>>(
        nullptr, w_ih_l1, w_hh_l1, b_ih_l1, b_hh_l1, w_fc, b_fc, out);
}

// round 4
// speedup vs baseline: 1.9794x; 1.0723x over previous
#include <cuda_runtime.h>

#define NB 256
#define NT 1024
#define ND0 32
#define NH 64

__device__ float g_h1[(size_t)NB * NT * NH];

using ull = unsigned long long;

__device__ __forceinline__ void ffma2(ull& d, ull a, ull b) {
    asm("fma.rn.f32x2 %0, %1, %2, %0;" : "+l"(d) : "l"(a), "l"(b));
}
__device__ __forceinline__ ull packf2(float x, float y) {
    ull r; asm("mov.b64 %0, {%1, %2};" : "=l"(r) : "f"(x), "f"(y)); return r;
}
__device__ __forceinline__ float2 unpackf2(ull v) {
    float2 f; asm("mov.b64 {%0, %1}, %2;" : "=f"(f.x), "=f"(f.y) : "l"(v)); return f;
}
__device__ __forceinline__ float ftanh(float x) {
    float y; asm("tanh.approx.f32 %0, %1;" : "=f"(y) : "f"(x)); return y;
}
__device__ __forceinline__ float fsig(float x) {
    return fmaf(0.5f, ftanh(0.5f * x), 0.5f);
}

// 512 threads, 2 samples/CTA. tid = [l(6) | q(1) | k(2)].
// Thread owns gates {64q+l, 128+64q+l}, k-th quarter of K, both samples.
// k-partials reduce via shfl_xor(1,2); (i,g)<->(f,o) exchange via shfl_xor(4).
// Double-buffered u => ONE barrier per step. No gate smem buffer.
template <int DIN, int LAYER>
__global__ __launch_bounds__(512) void lstm_layer(
    const float* __restrict__ xin,
    const float* __restrict__ w_ih,   // [256][DIN]
    const float* __restrict__ w_hh,   // [256][NH]
    const float* __restrict__ b_ih,
    const float* __restrict__ b_hh,
    const float* __restrict__ w_fc,   // [1][NH]  (LAYER==1)
    const float* __restrict__ b_fc,   // [1]      (LAYER==1)
    float* __restrict__ out)          // [B]      (LAYER==1)
{
    constexpr int U   = DIN + NH;     // 96 / 128
    constexpr int KS  = U / 4;        // k-slice floats: 24 / 32
    constexpr int NV  = KS / 4;       // ulonglong2 loads per slice: 6 / 8
    constexpr int W2  = KS / 2;       // f32x2 weights per gate: 12 / 16
    constexpr int SL  = KS + 4;       // padded slice stride (floats)
    constexpr int US  = 4 * SL;       // per-sample stride
    constexpr int BS  = 2 * US;       // per-buffer stride
    constexpr int NX4 = DIN / 4;

    __shared__ __align__(16) float ubuf[2 * BS];
    __shared__ float red[2 * NH];

    const int tid = threadIdx.x;
    const int k   = tid & 3;
    const int q   = (tid >> 2) & 1;
    const int l   = tid >> 3;           // 0..63
    const int b0  = blockIdx.x * 2;

    const int glo = 64 * q + l;         // q=0: i-gate, q=1: f-gate
    const int ghi = 128 + 64 * q + l;   // q=0: g-gate, q=1: o-gate
    const int ko  = k * KS;

    // ---- weight slices -> packed registers ----
    ull wlo[W2], whi[W2];
#pragma unroll
    for (int i = 0; i < W2; i++) {
        const int ka = ko + 2 * i, kb = ka + 1;
        const float a0 = (ka < DIN) ? w_ih[glo * DIN + ka] : w_hh[glo * NH + ka - DIN];
        const float a1 = (kb < DIN) ? w_ih[glo * DIN + kb] : w_hh[glo * NH + kb - DIN];
        const float c0 = (ka < DIN) ? w_ih[ghi * DIN + ka] : w_hh[ghi * NH + ka - DIN];
        const float c1 = (kb < DIN) ? w_ih[ghi * DIN + kb] : w_hh[ghi * NH + kb - DIN];
        wlo[i] = packf2(a0, a1);
        whi[i] = packf2(c0, c1);
    }
    const float blo = b_ih[glo] + b_hh[glo];
    const float bhi = b_ih[ghi] + b_hh[ghi];

    // roles
    const bool iscell = (q == 0) && (k < 2);
    const int  sel    = k;                         // cell's sample
    const bool isload = (q == 1) && (k >= 2) && (l < NX4);
    const int  lsamp  = k - 2;
    const int  hk     = DIN + l;
    const int  h_off  = (hk / KS) * SL + (hk % KS);     // skewed h slot
    const int  x_off  = ((4 * l) / KS) * SL + ((4 * l) % KS);

    const float* src = (LAYER == 0) ? xin  + (size_t)(b0 + lsamp) * NT * DIN
                                    : g_h1 + (size_t)(b0 + lsamp) * NT * NH;
    float* hdst0 = g_h1 + (size_t)(b0 + sel) * NT * NH;

    // zero both u buffers (h0 = 0 + padding), stage x_0, prefetch x_1
    for (int i = tid; i < 2 * BS; i += 512) ubuf[i] = 0.0f;
    __syncthreads();
    float4 xr;
    if (isload) {
        xr = *reinterpret_cast<const float4*>(src + 4 * l);
        *reinterpret_cast<float4*>(ubuf + lsamp * US + x_off) = xr;      // x_0 -> buf0
        xr = *reinterpret_cast<const float4*>(src + (size_t)DIN + 4 * l); // x_1
    }
    __syncthreads();

    float c_state = 0.0f, h_last = 0.0f;

    for (int t = 0; t < NT; t++) {
        const float* cur = ubuf + (t & 1) * BS;
        float*       nxt = ubuf + ((t + 1) & 1) * BS;

        const ulonglong2* u0 = reinterpret_cast<const ulonglong2*>(cur + k * SL);
        const ulonglong2* u1 = reinterpret_cast<const ulonglong2*>(cur + US + k * SL);

        ull alo0 = 0, ahi0 = 0, alo1 = 0, ahi1 = 0;
#pragma unroll
        for (int i = 0; i < NV; i++) {
            const ulonglong2 a = u0[i];
            const ulonglong2 b = u1[i];
            ffma2(alo0, a.x, wlo[2 * i]); ffma2(alo0, a.y, wlo[2 * i + 1]);
            ffma2(ahi0, a.x, whi[2 * i]); ffma2(ahi0, a.y, whi[2 * i + 1]);
            ffma2(alo1, b.x, wlo[2 * i]); ffma2(alo1, b.y, wlo[2 * i + 1]);
            ffma2(ahi1, b.x, whi[2 * i]); ffma2(ahi1, b.y, whi[2 * i + 1]);
        }
        float2 f;
        f = unpackf2(alo0); float vlo0 = f.x + f.y;
        f = unpackf2(ahi0); float vhi0 = f.x + f.y;
        f = unpackf2(alo1); float vlo1 = f.x + f.y;
        f = unpackf2(ahi1); float vhi1 = f.x + f.y;

        // reduce over the 4 k-slices (lanes xor 1, xor 2)
        vlo0 += __shfl_xor_sync(0xffffffffu, vlo0, 1);
        vhi0 += __shfl_xor_sync(0xffffffffu, vhi0, 1);
        vlo1 += __shfl_xor_sync(0xffffffffu, vlo1, 1);
        vhi1 += __shfl_xor_sync(0xffffffffu, vhi1, 1);
        vlo0 += __shfl_xor_sync(0xffffffffu, vlo0, 2);
        vhi0 += __shfl_xor_sync(0xffffffffu, vhi0, 2);
        vlo1 += __shfl_xor_sync(0xffffffffu, vlo1, 2);
        vhi1 += __shfl_xor_sync(0xffffffffu, vhi1, 2);
        vlo0 += blo; vhi0 += bhi; vlo1 += blo; vhi1 += bhi;

        // exchange with q-partner: q=0 gets (f,o), q=1 gets (i,g)
        const float plo0 = __shfl_xor_sync(0xffffffffu, vlo0, 4);
        const float plo1 = __shfl_xor_sync(0xffffffffu, vlo1, 4);
        const float phi0 = __shfl_xor_sync(0xffffffffu, vhi0, 4);
        const float phi1 = __shfl_xor_sync(0xffffffffu, vhi1, 4);

        if (iscell) {   // q==0 thread: own=(i,g), partner=(f,o); sample = sel
            const float gi = sel ? vlo1 : vlo0;
            const float gf = sel ? plo1 : plo0;
            const float gg = sel ? vhi1 : vhi0;
            const float go = sel ? phi1 : phi0;
            c_state = fsig(gf) * c_state + fsig(gi) * ftanh(gg);
            const float h = fsig(go) * ftanh(c_state);
            h_last = h;
            nxt[sel * US + h_off] = h;
            if (LAYER == 0) hdst0[t * NH + l] = h;
        }
        if (isload) {
            *reinterpret_cast<float4*>(nxt + lsamp * US + x_off) = xr;   // x_{t+1}
            if (t + 2 < NT)
                xr = *reinterpret_cast<const float4*>(src + (size_t)(t + 2) * DIN + 4 * l);
        }
        __syncthreads();
    }

    if (LAYER == 1) {
        if (iscell) red[sel * NH + l] = h_last * w_fc[l];
        __syncthreads();
        if (tid < 64) {
            const int s_ = tid >> 5, ln = tid & 31;
            float p = red[s_ * NH + ln] + red[s_ * NH + 32 + ln];
#pragma unroll
            for (int o = 16; o > 0; o >>= 1)
                p += __shfl_down_sync(0xffffffffu, p, o);
            if (ln == 0) out[b0 + s_] = fsig(p + b_fc[0]);
        }
    }
}

extern "C" void kernel_launch(void* const* d_in, const int* in_sizes, int n_in,
                              void* d_out, int out_size) {
    const float* x       = (const float*)d_in[0];
    const float* w_ih_l0 = (const float*)d_in[1];
    const float* w_hh_l0 = (const float*)d_in[2];
    const float* b_ih_l0 = (const float*)d_in[3];
    const float* b_hh_l0 = (const float*)d_in[4];
    const float* w_ih_l1 = (const float*)d_in[5];
    const float* w_hh_l1 = (const float*)d_in[6];
    const float* b_ih_l1 = (const float*)d_in[7];
    const float* b_hh_l1 = (const float*)d_in[8];
    const float* w_fc    = (const float*)d_in[9];
    const float* b_fc    = (const float*)d_in[10];
    float* out = (float*)d_out;

    lstm_layer<ND0, 0><<<NB / 2, 512>>>(
        x, w_ih_l0, w_hh_l0, b_ih_l0, b_hh_l0, nullptr, nullptr, nullptr);

    lstm_layer<NH, 1><<<NB / 2, 512>>>(
        nullptr, w_ih_l1, w_hh_l1, b_ih_l1, b_hh_l1, w_fc, b_fc, out);
}

// round 5
// speedup vs baseline: 2.5399x; 1.2832x over previous
#include <cuda_runtime.h>

#define NB 256
#define NT 1024
#define ND0 32
#define NH 64
#define NM (NB * NT)          // 262144 tokens

__device__ float g_h1[(size_t)NM * NH];     //  67 MB
__device__ float g_gx0[(size_t)NM * 256];   // 268 MB
__device__ float g_gx1[(size_t)NM * 256];   // 268 MB

using ull = unsigned long long;

__device__ __forceinline__ void ffma2(ull& d, ull a, ull b) {
    asm("fma.rn.f32x2 %0, %1, %2, %0;" : "+l"(d) : "l"(a), "l"(b));
}
__device__ __forceinline__ ull packf2(float x, float y) {
    ull r; asm("mov.b64 %0, {%1, %2};" : "=l"(r) : "f"(x), "f"(y)); return r;
}
__device__ __forceinline__ float2 unpackf2(ull v) {
    float2 f; asm("mov.b64 {%0, %1}, %2;" : "=f"(f.x), "=f"(f.y) : "l"(v)); return f;
}
__device__ __forceinline__ float ftanh(float x) {
    float y; asm("tanh.approx.f32 %0, %1;" : "=f"(y) : "f"(x)); return y;
}
__device__ __forceinline__ float fsig(float x) {
    return fmaf(0.5f, ftanh(0.5f * x), 0.5f);
}
__device__ __forceinline__ void cp_async16(void* s, const void* g) {
    unsigned sa = (unsigned)__cvta_generic_to_shared(s);
    asm volatile("cp.async.cg.shared.global [%0], [%1], 16;" :: "r"(sa), "l"(g));
}

// ============================ gate GEMM ============================
// gx[tok][g] = X[tok][:] . w_ih[g][:] + b_ih[g] + b_hh[g]
// CTA: 64 tokens x 256 gates; thread = 1 gate x 64 tokens (32 f32x2 accs).
template <int K>
__global__ __launch_bounds__(256) void gate_gemm(
    const float* __restrict__ X,     // [M][K]
    const float* __restrict__ w_ih,  // [256][K]
    const float* __restrict__ b_ih,
    const float* __restrict__ b_hh,
    float* __restrict__ gx)          // [M][256]
{
    constexpr int TP = 68;                      // padded row (floats)
    __shared__ __align__(16) float xT[K][TP];   // [k][token]

    const int g = threadIdx.x;
    const size_t tok0 = (size_t)blockIdx.x * 64;

    // load & transpose tile: 64 tokens x K
#pragma unroll
    for (int j = 0; j < K / 16; j++) {
        const int idx4 = threadIdx.x + j * 256;      // float4 index over [tok][K/4]
        const int tau  = idx4 / (K / 4);
        const int kc   = idx4 - tau * (K / 4);
        const float4 v = reinterpret_cast<const float4*>(X + (tok0 + tau) * K)[kc];
        xT[4 * kc + 0][tau] = v.x;
        xT[4 * kc + 1][tau] = v.y;
        xT[4 * kc + 2][tau] = v.z;
        xT[4 * kc + 3][tau] = v.w;
    }

    float w[K];
#pragma unroll
    for (int k = 0; k < K; k++) w[k] = w_ih[g * K + k];

    const float bias = b_ih[g] + b_hh[g];
    ull acc[32];
    const ull bp = packf2(bias, bias);
#pragma unroll
    for (int i = 0; i < 32; i++) acc[i] = bp;

    __syncthreads();

#pragma unroll 2
    for (int k = 0; k < K; k++) {
        const ull wb = packf2(w[k], w[k]);
        const ulonglong2* row = reinterpret_cast<const ulonglong2*>(&xT[k][0]);
#pragma unroll
        for (int i = 0; i < 16; i++) {
            const ulonglong2 v = row[i];
            ffma2(acc[2 * i],     v.x, wb);
            ffma2(acc[2 * i + 1], v.y, wb);
        }
    }

#pragma unroll
    for (int p = 0; p < 32; p++) {
        const float2 f = unpackf2(acc[p]);
        gx[(tok0 + 2 * p) * 256 + g]     = f.x;
        gx[(tok0 + 2 * p + 1) * 256 + g] = f.y;
    }
}

// ============================ recurrence ============================
// 256 threads, 2 samples/CTA. tid = [s(1)|l(6)|half(1)].
// Thread (l, half) owns gates {l, 64+l, 128+l, 192+l} (i,f,g,o of h-lane l),
// k-range [32*half, 32*half+32). One shfl_xor(1) k-reduce; half==0 does the
// cell inline (no gate exchange). gx streamed via 7-deep cp.async smem ring.
// ONE barrier per step, zero raw LDG in the loop.
template <int LAYER>
__global__ __launch_bounds__(256) void lstm_recur(
    const float* __restrict__ gx,    // [B][T][256] precomputed (incl. biases)
    const float* __restrict__ w_hh,  // [256][64]
    const float* __restrict__ w_fc,  // [1][64]   (LAYER==1)
    const float* __restrict__ b_fc,  // [1]       (LAYER==1)
    float* __restrict__ h1out,       // [B][T][64] (LAYER==0)
    float* __restrict__ out)         // [B]        (LAYER==1)
{
    constexpr int PF = 7;            // prefetch depth (slots = 8)

    __shared__ float hbuf[2][2][80];               // [buf][sample][64+pad]
    __shared__ __align__(16) float gxs[8][2][256]; // gx ring: 16 KB
    __shared__ float red[2][NH];

    const int tid  = threadIdx.x;
    const int s    = tid >> 7;       // sample
    const int r    = tid & 127;
    const int l    = r >> 1;         // h-lane 0..63
    const int half = r & 1;          // k-half
    const int b0   = blockIdx.x * 2;

    // ---- w_hh rows for gates i,f,g,o of lane l, my k-half -> registers ----
    ull w[4][16];
#pragma unroll
    for (int g4 = 0; g4 < 4; g4++) {
        const int row = 64 * g4 + l;
#pragma unroll
        for (int i = 0; i < 16; i++) {
            const int k = half * 32 + 2 * i;
            w[g4][i] = packf2(w_hh[row * NH + k], w_hh[row * NH + k + 1]);
        }
    }

    if (r < 80) { hbuf[0][s][r] = 0.0f; hbuf[1][s][r] = 0.0f; }

    // loaders: tid<128, each copies one 16B chunk of gx per step (2 samples)
    const int ls = tid >> 6, li = tid & 63;
    const float* gsrc = gx + ((size_t)(b0 + ls) * NT) * 256 + li * 4;

    if (tid < 128) {
#pragma unroll
        for (int p = 0; p < PF; p++) {
            cp_async16(&gxs[p][ls][li * 4], gsrc + (size_t)p * 256);
            asm volatile("cp.async.commit_group;");
        }
        asm volatile("cp.async.wait_group %0;" :: "n"(PF - 1));
    }
    __syncthreads();

    float c_state = 0.0f, h_last = 0.0f;

#pragma unroll 1
    for (int t = 0; t < NT; t++) {
        // gate biases (gx) for this step — slot t&7 is stable all step
        float gxi, gxf, gxg, gxo;
        if (!half) {
            const float* gb = &gxs[t & 7][s][0];
            gxi = gb[l]; gxf = gb[64 + l]; gxg = gb[128 + l]; gxo = gb[192 + l];
        }

        // dot: h_{t-1} . w_hh rows (my k-half)
        const ulonglong2* hc =
            reinterpret_cast<const ulonglong2*>(&hbuf[t & 1][s][half * 32]);
        ull a0 = 0, a1 = 0, a2 = 0, a3 = 0;
#pragma unroll
        for (int i = 0; i < 8; i++) {
            const ulonglong2 v = hc[i];
            ffma2(a0, v.x, w[0][2 * i]); ffma2(a0, v.y, w[0][2 * i + 1]);
            ffma2(a1, v.x, w[1][2 * i]); ffma2(a1, v.y, w[1][2 * i + 1]);
            ffma2(a2, v.x, w[2][2 * i]); ffma2(a2, v.y, w[2][2 * i + 1]);
            ffma2(a3, v.x, w[3][2 * i]); ffma2(a3, v.y, w[3][2 * i + 1]);
        }
        float2 f;
        f = unpackf2(a0); float s0 = f.x + f.y;
        f = unpackf2(a1); float s1 = f.x + f.y;
        f = unpackf2(a2); float s2 = f.x + f.y;
        f = unpackf2(a3); float s3 = f.x + f.y;
        s0 += __shfl_xor_sync(0xffffffffu, s0, 1);
        s1 += __shfl_xor_sync(0xffffffffu, s1, 1);
        s2 += __shfl_xor_sync(0xffffffffu, s2, 1);
        s3 += __shfl_xor_sync(0xffffffffu, s3, 1);

        if (!half) {
            const float gi = s0 + gxi;
            const float gf = s1 + gxf;
            const float gg = s2 + gxg;
            const float go = s3 + gxo;
            c_state = fsig(gf) * c_state + fsig(gi) * ftanh(gg);
            const float h = fsig(go) * ftanh(c_state);
            h_last = h;
            hbuf[(t + 1) & 1][s][l] = h;
            if (LAYER == 0)
                h1out[((size_t)(b0 + s) * NT + t) * NH + l] = h;
        }

        if (tid < 128) {
            if (t + PF < NT)
                cp_async16(&gxs[(t + PF) & 7][ls][li * 4],
                           gsrc + (size_t)(t + PF) * 256);
            asm volatile("cp.async.commit_group;");
            asm volatile("cp.async.wait_group %0;" :: "n"(PF - 1));
        }
        __syncthreads();
    }

    if (LAYER == 1) {
        if (!half) red[s][l] = h_last * w_fc[l];
        __syncthreads();
        if (tid < 64) {
            const int s_ = tid >> 5, ln = tid & 31;
            float p = red[s_][ln] + red[s_][ln + 32];
#pragma unroll
            for (int o = 16; o > 0; o >>= 1)
                p += __shfl_down_sync(0xffffffffu, p, o);
            if (ln == 0) out[b0 + s_] = fsig(p + b_fc[0]);
        }
    }
}

extern "C" void kernel_launch(void* const* d_in, const int* in_sizes, int n_in,
                              void* d_out, int out_size) {
    const float* x       = (const float*)d_in[0];
    const float* w_ih_l0 = (const float*)d_in[1];
    const float* w_hh_l0 = (const float*)d_in[2];
    const float* b_ih_l0 = (const float*)d_in[3];
    const float* b_hh_l0 = (const float*)d_in[4];
    const float* w_ih_l1 = (const float*)d_in[5];
    const float* w_hh_l1 = (const float*)d_in[6];
    const float* b_ih_l1 = (const float*)d_in[7];
    const float* b_hh_l1 = (const float*)d_in[8];
    const float* w_fc    = (const float*)d_in[9];
    const float* b_fc    = (const float*)d_in[10];
    float* out = (float*)d_out;

    float *gx0, *gx1, *h1;
    cudaGetSymbolAddress((void**)&gx0, g_gx0);
    cudaGetSymbolAddress((void**)&gx1, g_gx1);
    cudaGetSymbolAddress((void**)&h1,  g_h1);

    gate_gemm<ND0><<<NM / 64, 256>>>(x, w_ih_l0, b_ih_l0, b_hh_l0, gx0);
    lstm_recur<0><<<NB / 2, 256>>>(gx0, w_hh_l0, nullptr, nullptr, h1, nullptr);
    gate_gemm<NH><<<NM / 64, 256>>>(h1, w_ih_l1, b_ih_l1, b_hh_l1, gx1);
    lstm_recur<1><<<NB / 2, 256>>>(gx1, w_hh_l1, w_fc, b_fc, nullptr, out);
}

// round 6
// speedup vs baseline: 3.0987x; 1.2200x over previous
#include <cuda_runtime.h>

#define NB 256
#define NT 1024
#define ND0 32
#define NH 64
#define NM (NB * NT)

__device__ float g_gx0[(size_t)NM * 256];   // layer-0 gate pre-activations

using ull = unsigned long long;

__device__ __forceinline__ void ffma2(ull& d, ull a, ull b) {
    asm("fma.rn.f32x2 %0, %1, %2, %0;" : "+l"(d) : "l"(a), "l"(b));
}
__device__ __forceinline__ ull packf2(float x, float y) {
    ull r; asm("mov.b64 %0, {%1, %2};" : "=l"(r) : "f"(x), "f"(y)); return r;
}
__device__ __forceinline__ float2 unpackf2(ull v) {
    float2 f; asm("mov.b64 {%0, %1}, %2;" : "=f"(f.x), "=f"(f.y) : "l"(v)); return f;
}
__device__ __forceinline__ float ftanh(float x) {
    float y; asm("tanh.approx.f32 %0, %1;" : "=f"(y) : "f"(x)); return y;
}
__device__ __forceinline__ float fsig(float x) {
    return fmaf(0.5f, ftanh(0.5f * x), 0.5f);
}
__device__ __forceinline__ void cp_async16(void* s, const void* g) {
    unsigned sa = (unsigned)__cvta_generic_to_shared(s);
    asm volatile("cp.async.cg.shared.global [%0], [%1], 16;" :: "r"(sa), "l"(g));
}

// ===================== layer-0 gate GEMM (parallel over tokens) =====================
// gx[tok][g] = X[tok][:].w_ih[g][:] + b_ih[g] + b_hh[g]
template <int K>
__global__ __launch_bounds__(256) void gate_gemm(
    const float* __restrict__ X,     // [M][K]
    const float* __restrict__ w_ih,  // [256][K]
    const float* __restrict__ b_ih,
    const float* __restrict__ b_hh,
    float* __restrict__ gx)          // [M][256]
{
    constexpr int TP = 68;
    __shared__ __align__(16) float xT[K][TP];

    const int g = threadIdx.x;
    const size_t tok0 = (size_t)blockIdx.x * 64;

#pragma unroll
    for (int j = 0; j < K / 16; j++) {
        const int idx4 = threadIdx.x + j * 256;
        const int tau  = idx4 / (K / 4);
        const int kc   = idx4 - tau * (K / 4);
        const float4 v = reinterpret_cast<const float4*>(X + (tok0 + tau) * K)[kc];
        xT[4 * kc + 0][tau] = v.x;
        xT[4 * kc + 1][tau] = v.y;
        xT[4 * kc + 2][tau] = v.z;
        xT[4 * kc + 3][tau] = v.w;
    }

    float w[K];
#pragma unroll
    for (int k = 0; k < K; k++) w[k] = w_ih[g * K + k];

    const float bias = b_ih[g] + b_hh[g];
    ull acc[32];
    const ull bp = packf2(bias, bias);
#pragma unroll
    for (int i = 0; i < 32; i++) acc[i] = bp;

    __syncthreads();

#pragma unroll 2
    for (int k = 0; k < K; k++) {
        const ull wb = packf2(w[k], w[k]);
        const ulonglong2* row = reinterpret_cast<const ulonglong2*>(&xT[k][0]);
#pragma unroll
        for (int i = 0; i < 16; i++) {
            const ulonglong2 v = row[i];
            ffma2(acc[2 * i],     v.x, wb);
            ffma2(acc[2 * i + 1], v.y, wb);
        }
    }

#pragma unroll
    for (int p = 0; p < 32; p++) {
        const float2 f = unpackf2(acc[p]);
        gx[(tok0 + 2 * p) * 256 + g]     = f.x;
        gx[(tok0 + 2 * p + 1) * 256 + g] = f.y;
    }
}

// ===================== fused L0 + L1 recurrence (software pipeline, lag 1) ==========
// 384 threads, 2 samples/CTA.
//  warps 0-3 (tid<128):  L0 step t      — thread (l0=tid>>1, h0=tid&1): 4 gates,
//                         half of K=64, both samples; gx0 via cp.async ring.
//  warps 4-11 (tid>=128): L1 step t-1   — thread (l1=rt>>2, k1=rt&3): 4 gates of
//                         h-lane l1, quarter of K=128 over u=[h1(t-1); h2(t-2)],
//                         both samples; shfl_xor(1,2) k-reduce; cell inline.
// u ping-pong buffer: 4 slices of 32 floats (pad 4): slices 0-1 = h1, 2-3 = h2.
// ONE __syncthreads per super-step; 1025 super-steps. FC fused at the end.
__global__ __launch_bounds__(384) void lstm_fused(
    const float* __restrict__ gx0,    // [B][T][256] (with L0 biases)
    const float* __restrict__ w_hh0,  // [256][64]
    const float* __restrict__ w_ih1,  // [256][64]
    const float* __restrict__ w_hh1,  // [256][64]
    const float* __restrict__ b_ih1,  // [256]
    const float* __restrict__ b_hh1,  // [256]
    const float* __restrict__ w_fc,   // [64]
    const float* __restrict__ b_fc,   // [1]
    float* __restrict__ out)          // [B]
{
    constexpr int PF  = 7;
    constexpr int SL  = 36;           // padded slice stride (floats)
    constexpr int USZ = 4 * SL;       // per-sample u size

    __shared__ __align__(16) float ubuf[2][2][USZ];   // [buf][sample][u]
    __shared__ __align__(16) float gxs[8][2][256];    // gx0 ring
    __shared__ float red[2][NH];

    const int tid  = threadIdx.x;
    const int b0   = blockIdx.x * 2;
    const bool isL0 = (tid < 128);

    for (int i = tid; i < 2 * 2 * USZ; i += 384)
        (&ubuf[0][0][0])[i] = 0.0f;

    // ---- per-role weight registers (64 each) ----
    const int l0 = tid >> 1, h0 = tid & 1;       // L0 ids
    const int rt = tid - 128;
    const int k1 = rt & 3, l1 = rt >> 2;         // L1 ids

    ull w[4][16];
    float bi = 0.f, bf_ = 0.f, bg = 0.f, bo = 0.f;
    if (isL0) {
#pragma unroll
        for (int g4 = 0; g4 < 4; g4++) {
            const int row = 64 * g4 + l0;
#pragma unroll
            for (int i = 0; i < 16; i++) {
                const int k = 32 * h0 + 2 * i;
                w[g4][i] = packf2(w_hh0[row * NH + k], w_hh0[row * NH + k + 1]);
            }
        }
    } else {
#pragma unroll
        for (int g4 = 0; g4 < 4; g4++) {
            const int row = 64 * g4 + l1;
#pragma unroll
            for (int i = 0; i < 16; i++) {
                const int kk = 32 * k1 + 2 * i;     // 0..126, even
                const float a = (kk < 64) ? w_ih1[row * 64 + kk]
                                          : w_hh1[row * 64 + kk - 64];
                const float b = (kk < 64) ? w_ih1[row * 64 + kk + 1]
                                          : w_hh1[row * 64 + kk - 63];
                w[g4][i] = packf2(a, b);
            }
        }
        bi  = b_ih1[l1]       + b_hh1[l1];
        bf_ = b_ih1[64 + l1]  + b_hh1[64 + l1];
        bg  = b_ih1[128 + l1] + b_hh1[128 + l1];
        bo  = b_ih1[192 + l1] + b_hh1[192 + l1];
    }

    // gx0 loaders = the 128 L0 threads (16B each, 2 samples x 256 floats/step)
    const int ls = tid >> 6, li = tid & 63;
    const float* gsrc = gx0 + ((size_t)(b0 + ls) * NT) * 256 + li * 4;
    if (isL0) {
#pragma unroll
        for (int p = 0; p < PF; p++) {
            cp_async16(&gxs[p][ls][li * 4], gsrc + (size_t)p * 256);
            asm volatile("cp.async.commit_group;");
        }
        asm volatile("cp.async.wait_group %0;" :: "n"(PF - 1));
    }
    __syncthreads();

    float c0 = 0.f, c1 = 0.f;          // L0 cell states (h0==0 lanes)
    float c_s = 0.f, h_last = 0.f;     // L1 cell state  (k1<2 lanes)

#pragma unroll 1
    for (int t = 0; t <= NT; t++) {
        const int cb = t & 1, nb_ = (t + 1) & 1;

        if (isL0) {
            // ---- L0: h1[t] = cell(h1state . w_hh0 + gx0[t]) ----
            const ulonglong2* u0 = reinterpret_cast<const ulonglong2*>(&ubuf[cb][0][h0 * SL]);
            const ulonglong2* u1 = reinterpret_cast<const ulonglong2*>(&ubuf[cb][1][h0 * SL]);
            ull A[4][2];
#pragma unroll
            for (int g4 = 0; g4 < 4; g4++) { A[g4][0] = 0; A[g4][1] = 0; }
#pragma unroll
            for (int i = 0; i < 8; i++) {
                const ulonglong2 va = u0[i];
                const ulonglong2 vb = u1[i];
#pragma unroll
                for (int g4 = 0; g4 < 4; g4++) {
                    ffma2(A[g4][0], va.x, w[g4][2 * i]);
                    ffma2(A[g4][0], va.y, w[g4][2 * i + 1]);
                    ffma2(A[g4][1], vb.x, w[g4][2 * i]);
                    ffma2(A[g4][1], vb.y, w[g4][2 * i + 1]);
                }
            }
            float S[4][2];
#pragma unroll
            for (int g4 = 0; g4 < 4; g4++)
#pragma unroll
                for (int s = 0; s < 2; s++) {
                    const float2 f = unpackf2(A[g4][s]);
                    float v = f.x + f.y;
                    v += __shfl_xor_sync(0xffffffffu, v, 1);
                    S[g4][s] = v;
                }
            if (h0 == 0 && t < NT) {
                const float* gb0 = &gxs[t & 7][0][0];
                const float* gb1 = &gxs[t & 7][1][0];
                {
                    const float gi = S[0][0] + gb0[l0];
                    const float gf = S[1][0] + gb0[64 + l0];
                    const float gg = S[2][0] + gb0[128 + l0];
                    const float go = S[3][0] + gb0[192 + l0];
                    c0 = fsig(gf) * c0 + fsig(gi) * ftanh(gg);
                    ubuf[nb_][0][(l0 >> 5) * SL + (l0 & 31)] = fsig(go) * ftanh(c0);
                }
                {
                    const float gi = S[0][1] + gb1[l0];
                    const float gf = S[1][1] + gb1[64 + l0];
                    const float gg = S[2][1] + gb1[128 + l0];
                    const float go = S[3][1] + gb1[192 + l0];
                    c1 = fsig(gf) * c1 + fsig(gi) * ftanh(gg);
                    ubuf[nb_][1][(l0 >> 5) * SL + (l0 & 31)] = fsig(go) * ftanh(c1);
                }
            }
            // ring refill
            if (t + PF < NT)
                cp_async16(&gxs[(t + PF) & 7][ls][li * 4], gsrc + (size_t)(t + PF) * 256);
            asm volatile("cp.async.commit_group;");
            asm volatile("cp.async.wait_group %0;" :: "n"(PF - 1));
        } else {
            // ---- L1 (lag 1): h2[t-1] = cell([h1[t-1]; h2[t-2]] . W1 + b1) ----
            const ulonglong2* uA = reinterpret_cast<const ulonglong2*>(&ubuf[cb][0][k1 * SL]);
            const ulonglong2* uB = reinterpret_cast<const ulonglong2*>(&ubuf[cb][1][k1 * SL]);
            ull A[4][2];
#pragma unroll
            for (int g4 = 0; g4 < 4; g4++) { A[g4][0] = 0; A[g4][1] = 0; }
#pragma unroll
            for (int i = 0; i < 8; i++) {
                const ulonglong2 va = uA[i];
                const ulonglong2 vb = uB[i];
#pragma unroll
                for (int g4 = 0; g4 < 4; g4++) {
                    ffma2(A[g4][0], va.x, w[g4][2 * i]);
                    ffma2(A[g4][0], va.y, w[g4][2 * i + 1]);
                    ffma2(A[g4][1], vb.x, w[g4][2 * i]);
                    ffma2(A[g4][1], vb.y, w[g4][2 * i + 1]);
                }
            }
            float S[4][2];
#pragma unroll
            for (int g4 = 0; g4 < 4; g4++)
#pragma unroll
                for (int s = 0; s < 2; s++) {
                    const float2 f = unpackf2(A[g4][s]);
                    float v = f.x + f.y;
                    v += __shfl_xor_sync(0xffffffffu, v, 1);
                    v += __shfl_xor_sync(0xffffffffu, v, 2);
                    S[g4][s] = v;
                }
            if (t >= 1 && k1 < 2) {
                const int sel = k1;
                const float gi = S[0][sel] + bi;
                const float gf = S[1][sel] + bf_;
                const float gg = S[2][sel] + bg;
                const float go = S[3][sel] + bo;
                c_s = fsig(gf) * c_s + fsig(gi) * ftanh(gg);
                h_last = fsig(go) * ftanh(c_s);
                ubuf[nb_][sel][(2 + (l1 >> 5)) * SL + (l1 & 31)] = h_last;
            }
        }
        __syncthreads();
    }

    // ---- FC + sigmoid on h2[T-1] ----
    if (!isL0 && k1 < 2) red[k1][l1] = h_last * w_fc[l1];
    __syncthreads();
    if (tid < 64) {
        const int s_ = tid >> 5, ln = tid & 31;
        float p = red[s_][ln] + red[s_][ln + 32];
#pragma unroll
        for (int o = 16; o > 0; o >>= 1)
            p += __shfl_down_sync(0xffffffffu, p, o);
        if (ln == 0) out[b0 + s_] = fsig(p + b_fc[0]);
    }
}

extern "C" void kernel_launch(void* const* d_in, const int* in_sizes, int n_in,
                              void* d_out, int out_size) {
    const float* x       = (const float*)d_in[0];
    const float* w_ih_l0 = (const float*)d_in[1];
    const float* w_hh_l0 = (const float*)d_in[2];
    const float* b_ih_l0 = (const float*)d_in[3];
    const float* b_hh_l0 = (const float*)d_in[4];
    const float* w_ih_l1 = (const float*)d_in[5];
    const float* w_hh_l1 = (const float*)d_in[6];
    const float* b_ih_l1 = (const float*)d_in[7];
    const float* b_hh_l1 = (const float*)d_in[8];
    const float* w_fc    = (const float*)d_in[9];
    const float* b_fc    = (const float*)d_in[10];
    float* out = (float*)d_out;

    float* gx0;
    cudaGetSymbolAddress((void**)&gx0, g_gx0);

    gate_gemm<ND0><<<NM / 64, 256>>>(x, w_ih_l0, b_ih_l0, b_hh_l0, gx0);
    lstm_fused<<<NB / 2, 384>>>(gx0, w_hh_l0, w_ih_l1, w_hh_l1,
                                b_ih_l1, b_hh_l1, w_fc, b_fc, out);
}